// round 2
// baseline (speedup 1.0000x reference)
#include <cuda_runtime.h>
#include <cuda_bf16.h>

// Problem constants
#define PP 96     // panos
#define SS 128    // sats
#define HH 8      // heads
#define HD 32     // head dim
#define LL 16     // tokens per item (Lp == Ls == 16)
#define EE 256    // embedding
#define SCALE 0.17677669529663687f  // 1/sqrt(32)

typedef unsigned long long ull;

// ---------------- scratch (no allocs allowed) ----------------
__device__ float q_buf[PP * HH * LL * HD];      // [p][h][i][d]
__device__ float k_buf[SS * HH * HD * LL];      // [s][h][d][j]  (j innermost for f32x2 pairing)
__device__ float vw_buf[SS * HH * LL];          // [s][h][j]
__device__ float g_wveff[HH * EE];              // collapsed V weight
__device__ float g_bveff[HH];
__device__ float g_c1;                          // scalar bias term

// ---------------- f32x2 helpers (sm_103a FFMA2) ----------------
__device__ __forceinline__ ull fma_f32x2(ull a, ull b, ull c) {
    ull d;
    asm("fma.rn.f32x2 %0, %1, %2, %3;" : "=l"(d) : "l"(a), "l"(b), "l"(c));
    return d;
}
__device__ __forceinline__ ull pack_f32x2(float lo, float hi) {
    ull r;
    asm("mov.b64 %0, {%1, %2};" : "=l"(r) : "f"(lo), "f"(hi));
    return r;
}
__device__ __forceinline__ void unpack_f32x2(ull v, float& lo, float& hi) {
    asm("mov.b64 {%0, %1}, %2;" : "=f"(lo), "=f"(hi) : "l"(v));
}

// ---------------- Kernel A: collapse output-side weights ----------------
// w_eff[e]    = sum_f pw[f] * Wo[f,e]
// Wv_eff[h,e] = sum_d w_eff[h*32+d] * Wv[h*32+d, e]   (Wv = in_proj rows 512..767)
// bv_eff[h]   = sum_d w_eff[h*32+d] * bv[h*32+d]
// c           = sum_f pw[f]*bo[f] + pb
__global__ void prep_kernel(const float* __restrict__ in_w,
                            const float* __restrict__ in_b,
                            const float* __restrict__ ow,
                            const float* __restrict__ ob,
                            const float* __restrict__ pw,
                            const float* __restrict__ pb) {
    __shared__ float sweff[EE];
    int e = threadIdx.x;
    float a = 0.f;
    #pragma unroll 4
    for (int f = 0; f < EE; f++) a += pw[f] * ow[f * EE + e];
    sweff[e] = a;
    __syncthreads();

    #pragma unroll
    for (int h = 0; h < HH; h++) {
        const float* wv = in_w + (2 * EE + h * HD) * EE;  // Wv rows for head h
        float b = 0.f;
        #pragma unroll 4
        for (int d = 0; d < HD; d++) b += sweff[h * HD + d] * wv[d * EE + e];
        g_wveff[h * EE + e] = b;
    }
    if (threadIdx.x < HH) {
        int h = threadIdx.x;
        float b = 0.f;
        for (int d = 0; d < HD; d++) b += sweff[h * HD + d] * in_b[2 * EE + h * HD + d];
        g_bveff[h] = b;
    }
    if (threadIdx.x == 0) {
        float b = 0.f;
        for (int f = 0; f < EE; f++) b += pw[f] * ob[f];
        g_c1 = b + pb[0];
    }
}

// ---------------- Kernel B: Q / K projections + collapsed vw ----------------
// blocks 0..95: pano p -> q_buf ;  blocks 96..223: sat s -> k_buf + vw_buf
// 128 threads; thread = 2 output channels (c, c+128). One x LDS.128 feeds 4 FFMA2.
__global__ __launch_bounds__(128) void proj_kernel(const float* __restrict__ sat,
                                                   const float* __restrict__ pano,
                                                   const float* __restrict__ in_w,
                                                   const float* __restrict__ in_b) {
    __shared__ __align__(16) float xs[LL * 260];  // padded rows (260 = 16B-aligned, odd/4 banks)
    const int tid = threadIdx.x;
    const bool is_pano = (blockIdx.x < PP);
    const float* src = is_pano ? (pano + (size_t)blockIdx.x * LL * EE)
                               : (sat + (size_t)(blockIdx.x - PP) * LL * EE);

    // cooperative load of 16x256 token tile (1024 float4 / 128 threads)
    const float4* s4 = (const float4*)src;
    #pragma unroll
    for (int k = 0; k < 8; k++) {
        int v = tid + 128 * k;          // float4 index 0..1023
        int row = v >> 6, col4 = v & 63;
        *(float4*)(xs + row * 260 + col4 * 4) = s4[v];
    }
    __syncthreads();

    const int c0 = tid, c1 = tid + 128;
    const int wbase = is_pano ? 0 : EE * EE;
    const ulonglong2* W0p = (const ulonglong2*)(in_w + wbase + c0 * EE);
    const ulonglong2* W1p = (const ulonglong2*)(in_w + wbase + c1 * EE);
    const float b0 = in_b[(is_pano ? 0 : EE) + c0];
    const float b1 = in_b[(is_pano ? 0 : EE) + c1];

    ull acc0[LL], acc1[LL];
    #pragma unroll
    for (int i = 0; i < LL; i++) { acc0[i] = 0ull; acc1[i] = 0ull; }

    #pragma unroll 2
    for (int e4 = 0; e4 < EE / 4; e4++) {
        ulonglong2 w0 = W0p[e4];
        ulonglong2 w1 = W1p[e4];
        #pragma unroll
        for (int i = 0; i < LL; i++) {
            ulonglong2 x2 = *(const ulonglong2*)(xs + i * 260 + e4 * 4);
            acc0[i] = fma_f32x2(x2.x, w0.x, acc0[i]);
            acc0[i] = fma_f32x2(x2.y, w0.y, acc0[i]);
            acc1[i] = fma_f32x2(x2.x, w1.x, acc1[i]);
            acc1[i] = fma_f32x2(x2.y, w1.y, acc1[i]);
        }
    }

    float res0[LL], res1[LL];
    #pragma unroll
    for (int i = 0; i < LL; i++) {
        float lo, hi;
        unpack_f32x2(acc0[i], lo, hi); res0[i] = b0 + lo + hi;
        unpack_f32x2(acc1[i], lo, hi); res1[i] = b1 + lo + hi;
    }

    const int h0 = c0 >> 5, d0 = c0 & 31;
    const int h1 = c1 >> 5, d1 = c1 & 31;
    if (is_pano) {
        const int p = blockIdx.x;
        float* q0 = q_buf + ((p * HH + h0) * LL) * HD + d0;
        float* q1 = q_buf + ((p * HH + h1) * LL) * HD + d1;
        #pragma unroll
        for (int i = 0; i < LL; i++) { q0[i * HD] = res0[i]; q1[i * HD] = res1[i]; }
    } else {
        const int s = blockIdx.x - PP;
        float4* k0 = (float4*)(k_buf + ((s * HH + h0) * HD + d0) * LL);
        float4* k1 = (float4*)(k_buf + ((s * HH + h1) * HD + d1) * LL);
        #pragma unroll
        for (int t = 0; t < 4; t++) {
            k0[t] = make_float4(res0[4 * t], res0[4 * t + 1], res0[4 * t + 2], res0[4 * t + 3]);
            k1[t] = make_float4(res1[4 * t], res1[4 * t + 1], res1[4 * t + 2], res1[4 * t + 3]);
        }
        // collapsed V projection: vw[s,h,j] (128 threads = (h,j))
        int hh = tid >> 4, j = tid & 15;
        float a = g_bveff[hh];
        const float* wv = g_wveff + hh * EE;
        const float* xr = xs + j * 260;
        #pragma unroll 4
        for (int e = 0; e < EE; e++) a += xr[e] * wv[e];
        vw_buf[s * (HH * LL) + tid] = a;
    }
}

// ---------------- Kernel C: fused attention + collapsed epilogue ----------------
// grid (24, 16): block = 4 panos x 8 sats. 256 threads = 2 halves x (h,i);
// each thread scores 2 panos against the shared k-tile (1 LDS.128 -> 4 FFMA2).
__global__ __launch_bounds__(256, 2) void attn_kernel(float* __restrict__ out) {
    __shared__ __align__(16) float ks[HH * HD * LL];  // one sat: [h][d][j], 16KB
    __shared__ float svw[HH * LL];
    __shared__ float red[2][8];                        // [pano-in-pair][warp]

    const int tid = threadIdx.x;
    const int half = tid >> 7;          // pano-pair select
    const int t = tid & 127;
    const int h = t >> 4, i = t & 15;
    const int p0 = blockIdx.x * 4 + half * 2;   // this thread handles panos p0, p0+1
    const float c_val = g_c1;

    const float* qa_base = q_buf + (((p0 * HH + h) * LL) + i) * HD;
    const float* qb_base = qa_base + (size_t)HH * LL * HD;  // p0+1, same (h,i)

    const int s0 = blockIdx.y * 8;
    for (int ssi = 0; ssi < 8; ssi++) {
        const int s = s0 + ssi;

        // cooperative k-tile load (1024 float4 / 256 threads) + vw
        const float4* kb4 = (const float4*)(k_buf + (size_t)s * HH * HD * LL);
        float4* ks4 = (float4*)ks;
        #pragma unroll
        for (int r = 0; r < 4; r++) ks4[tid + 256 * r] = kb4[tid + 256 * r];
        if (tid < HH * LL) svw[tid] = vw_buf[s * (HH * LL) + tid];
        __syncthreads();

        ull acca[8], accb[8];
        #pragma unroll
        for (int a = 0; a < 8; a++) { acca[a] = 0ull; accb[a] = 0ull; }

        const ulonglong2* kp = (const ulonglong2*)(ks + h * (HD * LL));
        #pragma unroll
        for (int dh = 0; dh < 2; dh++) {          // d-halves keep q reg footprint at 32
            float qa[16], qb[16];
            const float4* qa4 = (const float4*)(qa_base + dh * 16);
            const float4* qb4 = (const float4*)(qb_base + dh * 16);
            #pragma unroll
            for (int kk = 0; kk < 4; kk++) {
                float4 va = qa4[kk];
                qa[4 * kk] = va.x; qa[4 * kk + 1] = va.y; qa[4 * kk + 2] = va.z; qa[4 * kk + 3] = va.w;
                float4 vb = qb4[kk];
                qb[4 * kk] = vb.x; qb[4 * kk + 1] = vb.y; qb[4 * kk + 2] = vb.z; qb[4 * kk + 3] = vb.w;
            }
            #pragma unroll
            for (int dd = 0; dd < 16; dd++) {
                const int d = dh * 16 + dd;
                ull qda = pack_f32x2(qa[dd], qa[dd]);
                ull qdb = pack_f32x2(qb[dd], qb[dd]);
                #pragma unroll
                for (int tt = 0; tt < 4; tt++) {
                    ulonglong2 kk = kp[d * 4 + tt];   // broadcast within h-group; reused by both panos
                    acca[2 * tt]     = fma_f32x2(kk.x, qda, acca[2 * tt]);
                    acca[2 * tt + 1] = fma_f32x2(kk.y, qda, acca[2 * tt + 1]);
                    accb[2 * tt]     = fma_f32x2(kk.x, qdb, accb[2 * tt]);
                    accb[2 * tt + 1] = fma_f32x2(kk.y, qdb, accb[2 * tt + 1]);
                }
            }
        }

        float sa[LL], sb[LL];
        #pragma unroll
        for (int a = 0; a < 8; a++) {
            unpack_f32x2(acca[a], sa[2 * a], sa[2 * a + 1]);
            unpack_f32x2(accb[a], sb[2 * a], sb[2 * a + 1]);
        }

        float ma = sa[0], mb = sb[0];
        #pragma unroll
        for (int j = 1; j < LL; j++) { ma = fmaxf(ma, sa[j]); mb = fmaxf(mb, sb[j]); }
        float suma = 0.f, vala = 0.f, sumb = 0.f, valb = 0.f;
        #pragma unroll
        for (int j = 0; j < LL; j++) {
            float w = svw[h * LL + j];
            float ea = __expf((sa[j] - ma) * SCALE);
            suma += ea; vala += ea * w;
            float eb = __expf((sb[j] - mb) * SCALE);
            sumb += eb; valb += eb * w;
        }
        float ra = vala / suma;
        float rb = valb / sumb;

        #pragma unroll
        for (int off = 16; off; off >>= 1) {
            ra += __shfl_xor_sync(0xffffffffu, ra, off);
            rb += __shfl_xor_sync(0xffffffffu, rb, off);
        }
        const int warp = tid >> 5, lane = tid & 31;
        if (lane == 0) { red[0][warp] = ra; red[1][warp] = rb; }
        __syncthreads();
        if (t < 2) {   // tid {0,1} handle panos p0,p0+1 of half 0; tid {128,129} of half 1
            const int w0 = half * 4;
            float tot = red[t][w0] + red[t][w0 + 1] + red[t][w0 + 2] + red[t][w0 + 3];
            out[(p0 + t) * SS + s] = c_val + tot * (1.0f / 16.0f);
        }
        __syncthreads();  // all threads past red/ks use before next sat's tile load
    }
}

// ---------------- launch ----------------
extern "C" void kernel_launch(void* const* d_in, const int* in_sizes, int n_in,
                              void* d_out, int out_size) {
    const float* sat  = (const float*)d_in[0];  // [128,16,256]
    const float* pano = (const float*)d_in[1];  // [96,16,256]
    const float* in_w = (const float*)d_in[2];  // [768,256]
    const float* in_b = (const float*)d_in[3];  // [768]
    const float* ow   = (const float*)d_in[4];  // [256,256]
    const float* ob   = (const float*)d_in[5];  // [256]
    const float* pw   = (const float*)d_in[6];  // [1,256]
    const float* pb   = (const float*)d_in[7];  // [1]
    float* out = (float*)d_out;                 // [96,128]

    prep_kernel<<<1, 256>>>(in_w, in_b, ow, ob, pw, pb);
    proj_kernel<<<PP + SS, 128>>>(sat, pano, in_w, in_b);
    attn_kernel<<<dim3(PP / 4, SS / 8), 256>>>(out);
}

// round 4
// speedup vs baseline: 1.1577x; 1.1577x over previous
#include <cuda_runtime.h>
#include <cuda_bf16.h>

// Problem constants
#define PP 96     // panos
#define SS 128    // sats
#define HH 8      // heads
#define HD 32     // head dim
#define LL 16     // tokens per item (Lp == Ls == 16)
#define EE 256    // embedding
#define SCALE 0.17677669529663687f  // 1/sqrt(32)

typedef unsigned long long ull;

// ---------------- scratch (no allocs allowed) ----------------
__device__ float q_buf[PP * HH * LL * HD];      // [p][h][i][d]
__device__ float k_buf[SS * HH * HD * LL];      // [s][h][d][j]  (j innermost for f32x2 pairing)
__device__ float vw_buf[SS * HH * LL];          // [s][h][j]
__device__ float g_weff_part[8][EE];            // partial w_eff sums (per f-chunk)
__device__ float g_wveff[HH * EE];              // collapsed V weight
__device__ float g_bveff[HH];
__device__ float g_c1;                          // scalar bias term

// ---------------- f32x2 helpers (sm_103a FFMA2) ----------------
__device__ __forceinline__ ull fma_f32x2(ull a, ull b, ull c) {
    ull d;
    asm("fma.rn.f32x2 %0, %1, %2, %3;" : "=l"(d) : "l"(a), "l"(b), "l"(c));
    return d;
}
__device__ __forceinline__ ull pack_f32x2(float lo, float hi) {
    ull r;
    asm("mov.b64 %0, {%1, %2};" : "=l"(r) : "f"(lo), "f"(hi));
    return r;
}
__device__ __forceinline__ void unpack_f32x2(ull v, float& lo, float& hi) {
    asm("mov.b64 {%0, %1}, %2;" : "=f"(lo), "=f"(hi) : "l"(v));
}

// ---------------- Kernel A1: partial w_eff + scalar c ----------------
// blocks 0..7: g_weff_part[b][e] = sum_{f in chunk b} pw[f] * ow[f,e]
// block 8:     g_c1 = sum_f pw[f]*ob[f] + pb   (block-parallel reduce)
__global__ __launch_bounds__(256) void prep1_kernel(const float* __restrict__ ow,
                                                    const float* __restrict__ ob,
                                                    const float* __restrict__ pw,
                                                    const float* __restrict__ pb) {
    const int e = threadIdx.x;
    const int b = blockIdx.x;
    if (b < 8) {
        float a = 0.f;
        #pragma unroll
        for (int k = 0; k < 32; k++) {
            int f = b * 32 + k;
            a += pw[f] * ow[f * EE + e];   // coalesced over e, MLP=32
        }
        g_weff_part[b][e] = a;
    } else {
        __shared__ float red[8];
        float v = pw[e] * ob[e];
        #pragma unroll
        for (int off = 16; off; off >>= 1) v += __shfl_xor_sync(0xffffffffu, v, off);
        const int warp = e >> 5, lane = e & 31;
        if (lane == 0) red[warp] = v;
        __syncthreads();
        if (e == 0) {
            float tot = 0.f;
            #pragma unroll
            for (int w = 0; w < 8; w++) tot += red[w];
            g_c1 = tot + pb[0];
        }
    }
}

// ---------------- Kernel A2: collapsed V weights ----------------
// block h: w_eff slice (32 vals) from partials, then
//   Wv_eff[h,e] = sum_d w_eff[h*32+d] * Wv[h*32+d, e]
//   bv_eff[h]   = sum_d w_eff[h*32+d] * bv[h*32+d]
__global__ __launch_bounds__(256) void prep2_kernel(const float* __restrict__ in_w,
                                                    const float* __restrict__ in_b) {
    __shared__ float wd[HD];
    const int h = blockIdx.x;
    const int e = threadIdx.x;

    if (e < HD) {
        float a = 0.f;
        #pragma unroll
        for (int b = 0; b < 8; b++) a += g_weff_part[b][h * HD + e];
        wd[e] = a;
    }
    __syncthreads();

    const float* wv = in_w + (2 * EE + h * HD) * EE;  // Wv rows for head h
    float a = 0.f;
    #pragma unroll
    for (int d = 0; d < HD; d++) a += wd[d] * wv[d * EE + e];  // coalesced, MLP=32
    g_wveff[h * EE + e] = a;

    if (e < 32) {   // warp 0: bv_eff[h] via lane-parallel reduce
        float v = wd[e] * in_b[2 * EE + h * HD + e];
        #pragma unroll
        for (int off = 16; off; off >>= 1) v += __shfl_xor_sync(0xffffffffu, v, off);
        if (e == 0) g_bveff[h] = v;
    }
}

// ---------------- Kernel B: Q / K projections + collapsed vw ----------------
// blocks 0..95: pano p -> q_buf ;  blocks 96..223: sat s -> k_buf + vw_buf
// 128 threads; thread = 2 output channels (c, c+128). One x LDS.128 feeds 4 FFMA2.
__global__ __launch_bounds__(128) void proj_kernel(const float* __restrict__ sat,
                                                   const float* __restrict__ pano,
                                                   const float* __restrict__ in_w,
                                                   const float* __restrict__ in_b) {
    __shared__ __align__(16) float xs[LL * 260];  // padded rows
    const int tid = threadIdx.x;
    const bool is_pano = (blockIdx.x < PP);
    const float* src = is_pano ? (pano + (size_t)blockIdx.x * LL * EE)
                               : (sat + (size_t)(blockIdx.x - PP) * LL * EE);

    // cooperative load of 16x256 token tile (1024 float4 / 128 threads)
    const float4* s4 = (const float4*)src;
    #pragma unroll
    for (int k = 0; k < 8; k++) {
        int v = tid + 128 * k;          // float4 index 0..1023
        int row = v >> 6, col4 = v & 63;
        *(float4*)(xs + row * 260 + col4 * 4) = s4[v];
    }
    __syncthreads();

    const int c0 = tid, c1 = tid + 128;
    const int wbase = is_pano ? 0 : EE * EE;
    const ulonglong2* W0p = (const ulonglong2*)(in_w + wbase + c0 * EE);
    const ulonglong2* W1p = (const ulonglong2*)(in_w + wbase + c1 * EE);
    const float b0 = in_b[(is_pano ? 0 : EE) + c0];
    const float b1 = in_b[(is_pano ? 0 : EE) + c1];

    ull acc0[LL], acc1[LL];
    #pragma unroll
    for (int i = 0; i < LL; i++) { acc0[i] = 0ull; acc1[i] = 0ull; }

    #pragma unroll 2
    for (int e4 = 0; e4 < EE / 4; e4++) {
        ulonglong2 w0 = W0p[e4];
        ulonglong2 w1 = W1p[e4];
        #pragma unroll
        for (int i = 0; i < LL; i++) {
            ulonglong2 x2 = *(const ulonglong2*)(xs + i * 260 + e4 * 4);
            acc0[i] = fma_f32x2(x2.x, w0.x, acc0[i]);
            acc0[i] = fma_f32x2(x2.y, w0.y, acc0[i]);
            acc1[i] = fma_f32x2(x2.x, w1.x, acc1[i]);
            acc1[i] = fma_f32x2(x2.y, w1.y, acc1[i]);
        }
    }

    float res0[LL], res1[LL];
    #pragma unroll
    for (int i = 0; i < LL; i++) {
        float lo, hi;
        unpack_f32x2(acc0[i], lo, hi); res0[i] = b0 + lo + hi;
        unpack_f32x2(acc1[i], lo, hi); res1[i] = b1 + lo + hi;
    }

    const int h0 = c0 >> 5, d0 = c0 & 31;
    const int h1 = c1 >> 5, d1 = c1 & 31;
    if (is_pano) {
        const int p = blockIdx.x;
        float* q0 = q_buf + ((p * HH + h0) * LL) * HD + d0;
        float* q1 = q_buf + ((p * HH + h1) * LL) * HD + d1;
        #pragma unroll
        for (int i = 0; i < LL; i++) { q0[i * HD] = res0[i]; q1[i * HD] = res1[i]; }
    } else {
        const int s = blockIdx.x - PP;
        float4* k0 = (float4*)(k_buf + ((s * HH + h0) * HD + d0) * LL);
        float4* k1 = (float4*)(k_buf + ((s * HH + h1) * HD + d1) * LL);
        #pragma unroll
        for (int t = 0; t < 4; t++) {
            k0[t] = make_float4(res0[4 * t], res0[4 * t + 1], res0[4 * t + 2], res0[4 * t + 3]);
            k1[t] = make_float4(res1[4 * t], res1[4 * t + 1], res1[4 * t + 2], res1[4 * t + 3]);
        }
        // collapsed V projection: vw[s,h,j] (128 threads = (h,j))
        int hh = tid >> 4, j = tid & 15;
        float a = g_bveff[hh];
        const float* wv = g_wveff + hh * EE;
        const float* xr = xs + j * 260;
        #pragma unroll 4
        for (int e = 0; e < EE; e++) a += xr[e] * wv[e];
        vw_buf[s * (HH * LL) + tid] = a;
    }
}

// ---------------- Kernel C: fused attention + collapsed epilogue ----------------
// grid (24, 16): block = 4 panos x 8 sats. 256 threads = 2 halves x (h,i);
// each thread scores 2 panos. k-tiles double-buffered: next sat prefetched into
// registers during compute, committed to the alternate smem buffer.
__global__ __launch_bounds__(256, 2) void attn_kernel(float* __restrict__ out) {
    __shared__ __align__(16) float ks[2][HH * HD * LL];  // 2 x 16KB
    __shared__ float svw[2][HH * LL];
    __shared__ float red[2][8];                           // [pano-in-pair][warp]

    const int tid = threadIdx.x;
    const int half = tid >> 7;          // pano-pair select
    const int t = tid & 127;
    const int h = t >> 4, i = t & 15;
    const int p0 = blockIdx.x * 4 + half * 2;   // this thread handles panos p0, p0+1
    const float c_val = g_c1;

    const float* qa_base = q_buf + (((p0 * HH + h) * LL) + i) * HD;
    const float* qb_base = qa_base + (size_t)HH * LL * HD;  // p0+1, same (h,i)

    const int s0 = blockIdx.y * 8;

    // preload first sat tile
    {
        const float4* kb4 = (const float4*)(k_buf + (size_t)s0 * HH * HD * LL);
        float4* d4 = (float4*)ks[0];
        #pragma unroll
        for (int r = 0; r < 4; r++) d4[tid + 256 * r] = kb4[tid + 256 * r];
        if (tid < HH * LL) svw[0][tid] = vw_buf[s0 * (HH * LL) + tid];
    }
    __syncthreads();

    int cur = 0;
    for (int ssi = 0; ssi < 8; ssi++) {
        const int s = s0 + ssi;

        // prefetch next sat tile into registers (overlaps with compute below)
        float4 pf[4];
        float pv = 0.f;
        if (ssi < 7) {
            const float4* kb4 = (const float4*)(k_buf + (size_t)(s + 1) * HH * HD * LL);
            #pragma unroll
            for (int r = 0; r < 4; r++) pf[r] = kb4[tid + 256 * r];
            if (tid < HH * LL) pv = vw_buf[(s + 1) * (HH * LL) + tid];
        }

        ull acca[8], accb[8];
        #pragma unroll
        for (int a = 0; a < 8; a++) { acca[a] = 0ull; accb[a] = 0ull; }

        const ulonglong2* kp = (const ulonglong2*)(ks[cur] + h * (HD * LL));
        #pragma unroll
        for (int dh = 0; dh < 2; dh++) {          // d-halves keep q reg footprint at 32
            float qa[16], qb[16];
            const float4* qa4 = (const float4*)(qa_base + dh * 16);
            const float4* qb4 = (const float4*)(qb_base + dh * 16);
            #pragma unroll
            for (int kk = 0; kk < 4; kk++) {
                float4 va = qa4[kk];
                qa[4 * kk] = va.x; qa[4 * kk + 1] = va.y; qa[4 * kk + 2] = va.z; qa[4 * kk + 3] = va.w;
                float4 vb = qb4[kk];
                qb[4 * kk] = vb.x; qb[4 * kk + 1] = vb.y; qb[4 * kk + 2] = vb.z; qb[4 * kk + 3] = vb.w;
            }
            #pragma unroll
            for (int dd = 0; dd < 16; dd++) {
                const int d = dh * 16 + dd;
                ull qda = pack_f32x2(qa[dd], qa[dd]);
                ull qdb = pack_f32x2(qb[dd], qb[dd]);
                #pragma unroll
                for (int tt = 0; tt < 4; tt++) {
                    ulonglong2 kk = kp[d * 4 + tt];   // broadcast within h-group; reused by both panos
                    acca[2 * tt]     = fma_f32x2(kk.x, qda, acca[2 * tt]);
                    acca[2 * tt + 1] = fma_f32x2(kk.y, qda, acca[2 * tt + 1]);
                    accb[2 * tt]     = fma_f32x2(kk.x, qdb, accb[2 * tt]);
                    accb[2 * tt + 1] = fma_f32x2(kk.y, qdb, accb[2 * tt + 1]);
                }
            }
        }

        float sa[LL], sb[LL];
        #pragma unroll
        for (int a = 0; a < 8; a++) {
            unpack_f32x2(acca[a], sa[2 * a], sa[2 * a + 1]);
            unpack_f32x2(accb[a], sb[2 * a], sb[2 * a + 1]);
        }

        float ma = sa[0], mb = sb[0];
        #pragma unroll
        for (int j = 1; j < LL; j++) { ma = fmaxf(ma, sa[j]); mb = fmaxf(mb, sb[j]); }
        float suma = 0.f, vala = 0.f, sumb = 0.f, valb = 0.f;
        #pragma unroll
        for (int j = 0; j < LL; j++) {
            float w = svw[cur][h * LL + j];
            float ea = __expf((sa[j] - ma) * SCALE);
            suma += ea; vala += ea * w;
            float eb = __expf((sb[j] - mb) * SCALE);
            sumb += eb; valb += eb * w;
        }
        float ra = vala / suma;
        float rb = valb / sumb;

        #pragma unroll
        for (int off = 16; off; off >>= 1) {
            ra += __shfl_xor_sync(0xffffffffu, ra, off);
            rb += __shfl_xor_sync(0xffffffffu, rb, off);
        }
        const int warp = tid >> 5, lane = tid & 31;
        if (lane == 0) { red[0][warp] = ra; red[1][warp] = rb; }
        __syncthreads();   // red visible; all reads of ks[cur] complete
        if (t < 2) {
            const int w0 = half * 4;
            float tot = red[t][w0] + red[t][w0 + 1] + red[t][w0 + 2] + red[t][w0 + 3];
            out[(p0 + t) * SS + s] = c_val + tot * (1.0f / 16.0f);
        }

        // commit prefetched tile into alternate buffer
        if (ssi < 7) {
            float4* d4 = (float4*)ks[cur ^ 1];
            #pragma unroll
            for (int r = 0; r < 4; r++) d4[tid + 256 * r] = pf[r];
            if (tid < HH * LL) svw[cur ^ 1][tid] = pv;
        }
        __syncthreads();   // new tile + red reads done before next iteration
        cur ^= 1;
    }
}

// ---------------- launch ----------------
extern "C" void kernel_launch(void* const* d_in, const int* in_sizes, int n_in,
                              void* d_out, int out_size) {
    const float* sat  = (const float*)d_in[0];  // [128,16,256]
    const float* pano = (const float*)d_in[1];  // [96,16,256]
    const float* in_w = (const float*)d_in[2];  // [768,256]
    const float* in_b = (const float*)d_in[3];  // [768]
    const float* ow   = (const float*)d_in[4];  // [256,256]
    const float* ob   = (const float*)d_in[5];  // [256]
    const float* pw   = (const float*)d_in[6];  // [1,256]
    const float* pb   = (const float*)d_in[7];  // [1]
    float* out = (float*)d_out;                 // [96,128]

    prep1_kernel<<<9, 256>>>(ow, ob, pw, pb);
    prep2_kernel<<<HH, 256>>>(in_w, in_b);
    proj_kernel<<<PP + SS, 128>>>(sat, pano, in_w, in_b);
    attn_kernel<<<dim3(PP / 4, SS / 8), 256>>>(out);
}